// round 6
// baseline (speedup 1.0000x reference)
#include <cuda_runtime.h>
#include <math.h>

#define B_  1024
#define N_  1024
#define M_  128
#define C_  1024
#define OUTF 390
#define EPS 1e-16f
#define KSPLIT 8
#define KCHUNK (C_ / KSPLIT)   // 128

// ---------------- scratch ----------------
__device__ float g_part[KSPLIT * B_ * OUTF];
__device__ float g_o[B_ * OUTF];     // GEMM output (k|beta|g|s0..2|gamma|e|a)
__device__ float g_scal[B_ * 8];     // beta,g,gamma,knorm,s0,s1,s2

// ---------------- K1: split-K SGEMM 1024 x 390 x 1024 ----------------
__global__ void k1_gemm(const float* __restrict__ A,
                        const float* __restrict__ Bm)
{
    __shared__ float As[16][65];
    __shared__ float Bs[16][68];

    const int tid = threadIdx.x;
    const int tx  = tid & 15;
    const int ty  = tid >> 4;
    const int row0 = blockIdx.y * 64;
    const int col0 = blockIdx.x * 64;
    const int ks   = blockIdx.z;
    const int kbeg = ks * KCHUNK;

    float acc[4][4];
#pragma unroll
    for (int i = 0; i < 4; i++)
#pragma unroll
        for (int j = 0; j < 4; j++) acc[i][j] = 0.f;

    const int ar  = tid >> 2;
    const int ac4 = (tid & 3) * 4;
    const int bkr = tid >> 4;
    const int bcc = (tid & 15) * 4;

    for (int k0 = kbeg; k0 < kbeg + KCHUNK; k0 += 16) {
        float4 av = *(const float4*)&A[(size_t)(row0 + ar) * C_ + k0 + ac4];
        As[ac4 + 0][ar] = av.x;
        As[ac4 + 1][ar] = av.y;
        As[ac4 + 2][ar] = av.z;
        As[ac4 + 3][ar] = av.w;
#pragma unroll
        for (int j = 0; j < 4; j++) {
            int col = col0 + bcc + j;
            Bs[bkr][bcc + j] = (col < OUTF) ? Bm[(size_t)(k0 + bkr) * OUTF + col] : 0.f;
        }
        __syncthreads();

#pragma unroll
        for (int kk = 0; kk < 16; kk++) {
            float ra[4], rb[4];
#pragma unroll
            for (int i = 0; i < 4; i++) ra[i] = As[kk][ty * 4 + i];
            float4 rb4 = *(const float4*)&Bs[kk][tx * 4];
            rb[0] = rb4.x; rb[1] = rb4.y; rb[2] = rb4.z; rb[3] = rb4.w;
#pragma unroll
            for (int i = 0; i < 4; i++)
#pragma unroll
                for (int j = 0; j < 4; j++) acc[i][j] = fmaf(ra[i], rb[j], acc[i][j]);
        }
        __syncthreads();
    }

    float* part = &g_part[(size_t)ks * B_ * OUTF];
#pragma unroll
    for (int i = 0; i < 4; i++) {
        int row = row0 + ty * 4 + i;
#pragma unroll
        for (int j = 0; j < 4; j++) {
            int col = col0 + tx * 4 + j;
            if (col < OUTF)
                part[(size_t)row * OUTF + col] = acc[i][j];
        }
    }
}

// ---------------- K1b: reduce partials + bias ----------------
__global__ void k1b_reduce(const float* __restrict__ bias)
{
    const int idx = blockIdx.x * 256 + threadIdx.x;
    if (idx >= B_ * OUTF) return;
    const int col = idx % OUTF;
    float s = 0.f;
#pragma unroll
    for (int ks = 0; ks < KSPLIT; ks++)
        s += g_part[(size_t)ks * B_ * OUTF + idx];
    g_o[idx] = s + bias[col];
}

// ---------------- K2: per-batch activations + k-norm ----------------
__device__ __forceinline__ float softplus_f(float x) {
    return (x > 0.f) ? (x + log1pf(expf(-x))) : log1pf(expf(x));
}
__device__ __forceinline__ float sigmoid_f(float x) {
    return 1.f / (1.f + expf(-x));
}

__global__ void k2_act()   // grid = B_, block = 128
{
    const int b   = blockIdx.x;
    const int tid = threadIdx.x;
    float* o = &g_o[(size_t)b * OUTF];

    float kv = o[tid];
    float ss = kv * kv;
#pragma unroll
    for (int off = 16; off > 0; off >>= 1)
        ss += __shfl_xor_sync(0xffffffffu, ss, off);
    __shared__ float red[4];
    if ((tid & 31) == 0) red[tid >> 5] = ss;
    __syncthreads();

    if (tid == 0) {
        float ksq = red[0] + red[1] + red[2] + red[3];
        float knorm = sqrtf(ksq);
        float beta  = softplus_f(o[M_]);
        float g     = sigmoid_f(o[M_ + 1]);
        float s0 = o[M_ + 2], s1 = o[M_ + 3], s2 = o[M_ + 4];
        float mx = fmaxf(s0, fmaxf(s1, s2));
        float e0 = expf(s0 - mx), e1 = expf(s1 - mx), e2 = expf(s2 - mx);
        float es = e0 + e1 + e2;
        float gamma = 1.f + softplus_f(o[M_ + 5]);
        float* sc = &g_scal[b * 8];
        sc[0] = beta; sc[1] = g; sc[2] = gamma; sc[3] = knorm;
        sc[4] = e0 / es; sc[5] = e1 / es; sc[6] = e2 / es;
    }
    o[M_ + 6 + tid] = sigmoid_f(o[M_ + 6 + tid]);
}

// ---------------- KF: fused sim + weighting + update, one CTA per batch ----------------
// 512 threads (16 warps, 64 rows/warp). SMEM padded so exactly 2 CTAs/SM:
// two independent barrier domains hide each other's softmax/sync bubbles.
// Pass 2 walks rows in REVERSE so most-recently-read rows (still in L2) go first.
__global__ void __launch_bounds__(512, 2)
kF_fused(const float* __restrict__ mem,
         const float* __restrict__ w_prev,
         float* __restrict__ w_out,
         float* __restrict__ out_mem)
{
    extern __shared__ float sh[];
    float* sk   = sh;            // 128
    float* se   = sk + 128;      // 128
    float* sa   = se + 128;      // 128
    float* slog = sa + 128;      // 1024: logits -> w_g (in place)
    float* warr = slog + 1024;   // 1024: final w
    float* sred = warr + 1024;   // 16

    const int b    = blockIdx.x;
    const int tid  = threadIdx.x;
    const int warp = tid >> 5;
    const int lane = tid & 31;

    if (tid < 128) {
        sk[tid] = g_o[(size_t)b * OUTF + tid];
        se[tid] = g_o[(size_t)b * OUTF + M_ + 6 + tid];
        sa[tid] = g_o[(size_t)b * OUTF + 2 * M_ + 6 + tid];
    }
    __syncthreads();

    const float beta  = g_scal[b * 8 + 0];
    const float g     = g_scal[b * 8 + 1];
    const float gamma = g_scal[b * 8 + 2];
    const float knorm = g_scal[b * 8 + 3];
    const float s0    = g_scal[b * 8 + 4];
    const float s1    = g_scal[b * 8 + 5];
    const float s2    = g_scal[b * 8 + 6];

    const float4 k4 = *(const float4*)&sk[lane * 4];
    const float4 ev = *(const float4*)&se[lane * 4];
    const float4 av = *(const float4*)&sa[lane * 4];

    const float* memb = mem + (size_t)b * N_ * M_;

    // ---- pass 1: logits = beta * cos(mem_row, k); 16 warps x 64 rows ----
#pragma unroll 4
    for (int i0 = 0; i0 < 64; i0 += 4) {
        const int nbase = warp * 64 + i0;
        float dot[4], ssq[4];
#pragma unroll
        for (int i = 0; i < 4; i++) {
            const float4 mv = *(const float4*)&memb[(size_t)(nbase + i) * M_ + lane * 4];
            dot[i] = mv.x * k4.x + mv.y * k4.y + mv.z * k4.z + mv.w * k4.w;
            ssq[i] = mv.x * mv.x + mv.y * mv.y + mv.z * mv.z + mv.w * mv.w;
        }
#pragma unroll
        for (int off = 16; off > 0; off >>= 1) {
#pragma unroll
            for (int i = 0; i < 4; i++) {
                dot[i] += __shfl_xor_sync(0xffffffffu, dot[i], off);
                ssq[i] += __shfl_xor_sync(0xffffffffu, ssq[i], off);
            }
        }
        if (lane < 4) {
            const int i = lane;
            float sim = dot[i] / (sqrtf(ssq[i]) * knorm + EPS);
            slog[nbase + i] = beta * sim;
        }
    }
    __syncthreads();

    // ---- softmax -> gate -> shift conv -> sharpen (2 elems per thread) ----
    float x[2];
    float lmax = -1e30f;
#pragma unroll
    for (int j = 0; j < 2; j++) {
        x[j] = slog[tid + 512 * j];
        lmax = fmaxf(lmax, x[j]);
    }
#pragma unroll
    for (int off = 16; off > 0; off >>= 1)
        lmax = fmaxf(lmax, __shfl_xor_sync(0xffffffffu, lmax, off));
    if (lane == 0) sred[warp] = lmax;
    __syncthreads();
    float bmax = sred[0];
#pragma unroll
    for (int k = 1; k < 16; k++) bmax = fmaxf(bmax, sred[k]);

    float p[2];
    float lsum = 0.f;
#pragma unroll
    for (int j = 0; j < 2; j++) { p[j] = expf(x[j] - bmax); lsum += p[j]; }
#pragma unroll
    for (int off = 16; off > 0; off >>= 1)
        lsum += __shfl_xor_sync(0xffffffffu, lsum, off);
    __syncthreads();
    if (lane == 0) sred[warp] = lsum;
    __syncthreads();
    float bsum = 0.f;
#pragma unroll
    for (int k = 0; k < 16; k++) bsum += sred[k];
    const float inv = 1.f / bsum;

    const float* wp = &w_prev[(size_t)b * N_];
#pragma unroll
    for (int j = 0; j < 2; j++) {
        const int i = tid + 512 * j;
        slog[i] = g * (p[j] * inv) + (1.f - g) * wp[i];   // w_g in place
    }
    __syncthreads();

    float wpow[2];
    float lsum2 = 0.f;
#pragma unroll
    for (int j = 0; j < 2; j++) {
        const int i = tid + 512 * j;
        float wt = s0 * slog[(i + N_ - 1) & (N_ - 1)] + s1 * slog[i]
                 + s2 * slog[(i + 1) & (N_ - 1)];
        wpow[j] = powf(wt + EPS, gamma);
        lsum2 += wpow[j];
    }
#pragma unroll
    for (int off = 16; off > 0; off >>= 1)
        lsum2 += __shfl_xor_sync(0xffffffffu, lsum2, off);
    __syncthreads();
    if (lane == 0) sred[warp] = lsum2;
    __syncthreads();
    float bsum2 = 0.f;
#pragma unroll
    for (int k = 0; k < 16; k++) bsum2 += sred[k];
    const float inv2 = 1.f / (bsum2 + EPS);

#pragma unroll
    for (int j = 0; j < 2; j++) {
        const int i = tid + 512 * j;
        const float wv = wpow[j] * inv2;
        warr[i] = wv;
        w_out[(size_t)b * N_ + i] = wv;
    }
    __syncthreads();

    // ---- pass 2 (REVERSE order): new_mem = mem*(1 - w e) + w a ----
    float* outb = out_mem + (size_t)b * N_ * M_;
#pragma unroll 4
    for (int i0 = 60; i0 >= 0; i0 -= 4) {
        const int nbase = warp * 64 + i0;
#pragma unroll
        for (int i = 3; i >= 0; i--) {
            const int n = nbase + i;
            const float w_ = warr[n];
            const size_t off = (size_t)n * M_ + lane * 4;
            float4 mv = __ldcs((const float4*)&memb[off]);   // last use
            float4 r;
            r.x = mv.x * (1.f - w_ * ev.x) + w_ * av.x;
            r.y = mv.y * (1.f - w_ * ev.y) + w_ * av.y;
            r.z = mv.z * (1.f - w_ * ev.z) + w_ * av.z;
            r.w = mv.w * (1.f - w_ * ev.w) + w_ * av.w;
            __stcs((float4*)&outb[off], r);                  // evict-first write
        }
    }
}

// ---------------- launch ----------------
extern "C" void kernel_launch(void* const* d_in, const int* in_sizes, int n_in,
                              void* d_out, int out_size)
{
    const float* emb    = (const float*)d_in[0];
    const float* w_prev = (const float*)d_in[1];
    const float* mem    = (const float*)d_in[2];
    const float* fc_w   = (const float*)d_in[3];
    const float* fc_b   = (const float*)d_in[4];

    float* out_w   = (float*)d_out;
    float* out_mem = out_w + (size_t)B_ * N_;

    dim3 g1((OUTF + 63) / 64, B_ / 64, KSPLIT);
    k1_gemm<<<g1, 256>>>(emb, fc_w);
    k1b_reduce<<<(B_ * OUTF + 255) / 256, 256>>>(fc_b);
    k2_act<<<B_, 128>>>();

    // pad SMEM to ~90 KB -> exactly 2 CTAs/SM
    const int smemF = 90 * 1024;
    cudaFuncSetAttribute(kF_fused, cudaFuncAttributeMaxDynamicSharedMemorySize, smemF);
    kF_fused<<<B_, 512, smemF>>>(mem, w_prev, out_w, out_mem);
}

// round 7
// speedup vs baseline: 1.1861x; 1.1861x over previous
#include <cuda_runtime.h>
#include <math.h>

#define B_  1024
#define N_  1024
#define M_  128
#define C_  1024
#define OUTF 390
#define EPS 1e-16f
#define KSPLIT 8
#define KCHUNK (C_ / KSPLIT)   // 128

// ---------------- scratch ----------------
__device__ float g_part[KSPLIT * B_ * OUTF];
__device__ float g_o[B_ * OUTF];     // (k|beta|g|s0..2|gamma|e|a), e sigmoided
__device__ float g_scal[B_ * 8];     // beta,g,gamma,knorm,s0,s1,s2

// ---------------- K1: split-K SGEMM 1024 x 390 x 1024 ----------------
__global__ void k1_gemm(const float* __restrict__ A,
                        const float* __restrict__ Bm)
{
    __shared__ float As[16][65];
    __shared__ float Bs[16][68];

    const int tid = threadIdx.x;
    const int tx  = tid & 15;
    const int ty  = tid >> 4;
    const int row0 = blockIdx.y * 64;
    const int col0 = blockIdx.x * 64;
    const int kbeg = blockIdx.z * KCHUNK;

    float acc[4][4];
#pragma unroll
    for (int i = 0; i < 4; i++)
#pragma unroll
        for (int j = 0; j < 4; j++) acc[i][j] = 0.f;

    const int ar  = tid >> 2;
    const int ac4 = (tid & 3) * 4;
    const int bkr = tid >> 4;
    const int bcc = (tid & 15) * 4;

    for (int k0 = kbeg; k0 < kbeg + KCHUNK; k0 += 16) {
        float4 av = *(const float4*)&A[(size_t)(row0 + ar) * C_ + k0 + ac4];
        As[ac4 + 0][ar] = av.x;
        As[ac4 + 1][ar] = av.y;
        As[ac4 + 2][ar] = av.z;
        As[ac4 + 3][ar] = av.w;
#pragma unroll
        for (int j = 0; j < 4; j++) {
            int col = col0 + bcc + j;
            Bs[bkr][bcc + j] = (col < OUTF) ? Bm[(size_t)(k0 + bkr) * OUTF + col] : 0.f;
        }
        __syncthreads();

#pragma unroll
        for (int kk = 0; kk < 16; kk++) {
            float ra[4], rb[4];
#pragma unroll
            for (int i = 0; i < 4; i++) ra[i] = As[kk][ty * 4 + i];
            float4 rb4 = *(const float4*)&Bs[kk][tx * 4];
            rb[0] = rb4.x; rb[1] = rb4.y; rb[2] = rb4.z; rb[3] = rb4.w;
#pragma unroll
            for (int i = 0; i < 4; i++)
#pragma unroll
                for (int j = 0; j < 4; j++) acc[i][j] = fmaf(ra[i], rb[j], acc[i][j]);
        }
        __syncthreads();
    }

    float* part = &g_part[(size_t)blockIdx.z * B_ * OUTF];
#pragma unroll
    for (int i = 0; i < 4; i++) {
        int row = row0 + ty * 4 + i;
#pragma unroll
        for (int j = 0; j < 4; j++) {
            int col = col0 + tx * 4 + j;
            if (col < OUTF)
                part[(size_t)row * OUTF + col] = acc[i][j];
        }
    }
}

// ---------------- K2: fused split-K reduce + bias + activations ----------------
__device__ __forceinline__ float softplus_f(float x) {
    return (x > 0.f) ? (x + log1pf(expf(-x))) : log1pf(expf(x));
}
__device__ __forceinline__ float sigmoid_f(float x) {
    return 1.f / (1.f + expf(-x));
}

__global__ void k2_redact(const float* __restrict__ bias)  // grid=B_, block=256
{
    const int b   = blockIdx.x;
    const int tid = threadIdx.x;
    __shared__ float so[OUTF];
    __shared__ float red[8];

    // reduce partials + bias for this row
    for (int col = tid; col < OUTF; col += 256) {
        float s = bias[col];
#pragma unroll
        for (int ks = 0; ks < KSPLIT; ks++)
            s += g_part[(size_t)ks * B_ * OUTF + (size_t)b * OUTF + col];
        so[col] = s;
    }
    __syncthreads();

    // k-norm over first 128
    float ss = 0.f;
    if (tid < 128) { float kv = so[tid]; ss = kv * kv; }
#pragma unroll
    for (int off = 16; off > 0; off >>= 1)
        ss += __shfl_xor_sync(0xffffffffu, ss, off);
    if ((tid & 31) == 0) red[tid >> 5] = ss;
    __syncthreads();

    if (tid == 0) {
        float knorm = sqrtf(red[0] + red[1] + red[2] + red[3]);
        float beta  = softplus_f(so[M_]);
        float g     = sigmoid_f(so[M_ + 1]);
        float s0 = so[M_ + 2], s1 = so[M_ + 3], s2 = so[M_ + 4];
        float mx = fmaxf(s0, fmaxf(s1, s2));
        float e0 = expf(s0 - mx), e1 = expf(s1 - mx), e2 = expf(s2 - mx);
        float es = e0 + e1 + e2;
        float gamma = 1.f + softplus_f(so[M_ + 5]);
        float* sc = &g_scal[b * 8];
        sc[0] = beta; sc[1] = g; sc[2] = gamma; sc[3] = knorm;
        sc[4] = e0 / es; sc[5] = e1 / es; sc[6] = e2 / es;
    }

    // write k, sigmoid(e), a to g_o
    float* o = &g_o[(size_t)b * OUTF];
    for (int col = tid; col < OUTF; col += 256) {
        float v = so[col];
        if (col >= M_ + 6 && col < 2 * M_ + 6) v = sigmoid_f(v);
        o[col] = v;
    }
}

// ---------------- KF: fused sim + weighting + update ----------------
// 1024 threads, 1 CTA/SM (SMEM padded): 148 resident batch slices (76MB) stay
// L2-resident between pass 1 (read) and pass 2 (read __ldcs, write __stcs).
// Pass 1 uses 8-lanes-per-row layout: 6 shuffles per 4 rows instead of 40.
__global__ void __launch_bounds__(1024, 1)
kF_fused(const float* __restrict__ mem,
         const float* __restrict__ w_prev,
         float* __restrict__ w_out,
         float* __restrict__ out_mem)
{
    extern __shared__ float sh[];
    float* sk   = sh;            // 128
    float* se   = sk + 128;      // 128
    float* sa   = se + 128;      // 128
    float* slog = sa + 128;      // 1024
    float* warr = slog + 1024;   // 1024
    float* sred = warr + 1024;   // 32

    const int b    = blockIdx.x;
    const int tid  = threadIdx.x;
    const int warp = tid >> 5;
    const int lane = tid & 31;

    if (tid < 128) {
        sk[tid] = g_o[(size_t)b * OUTF + tid];
        se[tid] = g_o[(size_t)b * OUTF + M_ + 6 + tid];
        sa[tid] = g_o[(size_t)b * OUTF + 2 * M_ + 6 + tid];
    }
    __syncthreads();

    const float beta  = g_scal[b * 8 + 0];
    const float g     = g_scal[b * 8 + 1];
    const float gamma = g_scal[b * 8 + 2];
    const float knorm = g_scal[b * 8 + 3];
    const float s0    = g_scal[b * 8 + 4];
    const float s1    = g_scal[b * 8 + 5];
    const float s2    = g_scal[b * 8 + 6];

    const float* memb = mem + (size_t)b * N_ * M_;

    // ---- pass 1: 8 lanes per row; lane sub = row-in-group, qc = col quarter base
    const int sub = lane >> 3;          // 0..3
    const int qc  = (lane & 7) * 4;     // 0,4,..,28
    float kq[4][4];                     // k values this lane needs: cols qc+32*q+0..3
#pragma unroll
    for (int q = 0; q < 4; q++) {
        const float4 kv = *(const float4*)&sk[qc + 32 * q];
        kq[q][0] = kv.x; kq[q][1] = kv.y; kq[q][2] = kv.z; kq[q][3] = kv.w;
    }

#pragma unroll
    for (int i0 = 0; i0 < 32; i0 += 8) {
        const int n0 = warp * 32 + i0 + sub;
        const int n1 = n0 + 4;
        float4 mv0[4], mv1[4];
#pragma unroll
        for (int q = 0; q < 4; q++) {
            mv0[q] = *(const float4*)&memb[(size_t)n0 * M_ + qc + 32 * q];
            mv1[q] = *(const float4*)&memb[(size_t)n1 * M_ + qc + 32 * q];
        }
        float dot0 = 0.f, ssq0 = 0.f, dot1 = 0.f, ssq1 = 0.f;
#pragma unroll
        for (int q = 0; q < 4; q++) {
            dot0 = fmaf(mv0[q].x, kq[q][0], dot0); ssq0 = fmaf(mv0[q].x, mv0[q].x, ssq0);
            dot0 = fmaf(mv0[q].y, kq[q][1], dot0); ssq0 = fmaf(mv0[q].y, mv0[q].y, ssq0);
            dot0 = fmaf(mv0[q].z, kq[q][2], dot0); ssq0 = fmaf(mv0[q].z, mv0[q].z, ssq0);
            dot0 = fmaf(mv0[q].w, kq[q][3], dot0); ssq0 = fmaf(mv0[q].w, mv0[q].w, ssq0);
            dot1 = fmaf(mv1[q].x, kq[q][0], dot1); ssq1 = fmaf(mv1[q].x, mv1[q].x, ssq1);
            dot1 = fmaf(mv1[q].y, kq[q][1], dot1); ssq1 = fmaf(mv1[q].y, mv1[q].y, ssq1);
            dot1 = fmaf(mv1[q].z, kq[q][2], dot1); ssq1 = fmaf(mv1[q].z, mv1[q].z, ssq1);
            dot1 = fmaf(mv1[q].w, kq[q][3], dot1); ssq1 = fmaf(mv1[q].w, mv1[q].w, ssq1);
        }
#pragma unroll
        for (int off = 4; off > 0; off >>= 1) {
            dot0 += __shfl_xor_sync(0xffffffffu, dot0, off);
            ssq0 += __shfl_xor_sync(0xffffffffu, ssq0, off);
            dot1 += __shfl_xor_sync(0xffffffffu, dot1, off);
            ssq1 += __shfl_xor_sync(0xffffffffu, ssq1, off);
        }
        if ((lane & 7) == 0) {
            slog[n0] = beta * (dot0 / (sqrtf(ssq0) * knorm + EPS));
            slog[n1] = beta * (dot1 / (sqrtf(ssq1) * knorm + EPS));
        }
    }
    __syncthreads();

    // ---- softmax -> gate -> shift conv -> sharpen (1 elem per thread) ----
    float x = slog[tid];
    float lmax = x;
#pragma unroll
    for (int off = 16; off > 0; off >>= 1)
        lmax = fmaxf(lmax, __shfl_xor_sync(0xffffffffu, lmax, off));
    if (lane == 0) sred[warp] = lmax;
    __syncthreads();
    float bmax = sred[0];
#pragma unroll
    for (int k = 1; k < 32; k++) bmax = fmaxf(bmax, sred[k]);

    float p = expf(x - bmax);
    float lsum = p;
#pragma unroll
    for (int off = 16; off > 0; off >>= 1)
        lsum += __shfl_xor_sync(0xffffffffu, lsum, off);
    __syncthreads();
    if (lane == 0) sred[warp] = lsum;
    __syncthreads();
    float bsum = 0.f;
#pragma unroll
    for (int k = 0; k < 32; k++) bsum += sred[k];
    const float inv = 1.f / bsum;

    slog[tid] = g * (p * inv) + (1.f - g) * w_prev[(size_t)b * N_ + tid];   // w_g
    __syncthreads();

    float wt = s0 * slog[(tid + N_ - 1) & (N_ - 1)] + s1 * slog[tid]
             + s2 * slog[(tid + 1) & (N_ - 1)];
    float wpow = powf(wt + EPS, gamma);
    float lsum2 = wpow;
#pragma unroll
    for (int off = 16; off > 0; off >>= 1)
        lsum2 += __shfl_xor_sync(0xffffffffu, lsum2, off);
    __syncthreads();
    if (lane == 0) sred[warp] = lsum2;
    __syncthreads();
    float bsum2 = 0.f;
#pragma unroll
    for (int k = 0; k < 32; k++) bsum2 += sred[k];
    const float inv2 = 1.f / (bsum2 + EPS);

    const float wv = wpow * inv2;
    warr[tid] = wv;
    w_out[(size_t)b * N_ + tid] = wv;
    __syncthreads();

    // ---- pass 2: new_mem = mem*(1 - w e) + w a (rows are L2 hits) ----
    const float4 ev = *(const float4*)&se[lane * 4];
    const float4 av = *(const float4*)&sa[lane * 4];
    float* outb = out_mem + (size_t)b * N_ * M_;
#pragma unroll
    for (int i0 = 0; i0 < 32; i0 += 4) {
        const int nbase = warp * 32 + i0;
#pragma unroll
        for (int i = 0; i < 4; i++) {
            const int n = nbase + i;
            const float w_ = warr[n];
            const size_t off = (size_t)n * M_ + lane * 4;
            float4 mv = __ldcs((const float4*)&memb[off]);
            float4 r;
            r.x = mv.x * (1.f - w_ * ev.x) + w_ * av.x;
            r.y = mv.y * (1.f - w_ * ev.y) + w_ * av.y;
            r.z = mv.z * (1.f - w_ * ev.z) + w_ * av.z;
            r.w = mv.w * (1.f - w_ * ev.w) + w_ * av.w;
            __stcs((float4*)&outb[off], r);
        }
    }
}

// ---------------- launch ----------------
extern "C" void kernel_launch(void* const* d_in, const int* in_sizes, int n_in,
                              void* d_out, int out_size)
{
    const float* emb    = (const float*)d_in[0];
    const float* w_prev = (const float*)d_in[1];
    const float* mem    = (const float*)d_in[2];
    const float* fc_w   = (const float*)d_in[3];
    const float* fc_b   = (const float*)d_in[4];

    float* out_w   = (float*)d_out;
    float* out_mem = out_w + (size_t)B_ * N_;

    dim3 g1((OUTF + 63) / 64, B_ / 64, KSPLIT);
    k1_gemm<<<g1, 256>>>(emb, fc_w);
    k2_redact<<<B_, 256>>>(fc_b);

    const int smemF = 120 * 1024;   // force 1 CTA/SM
    cudaFuncSetAttribute(kF_fused, cudaFuncAttributeMaxDynamicSharedMemorySize, smemF);
    kF_fused<<<B_, 1024, smemF>>>(mem, w_prev, out_w, out_mem);
}

// round 10
// speedup vs baseline: 1.2725x; 1.0728x over previous
#include <cuda_runtime.h>
#include <math.h>

#define B_  1024
#define N_  1024
#define M_  128
#define C_  1024
#define OUTF 390
#define EPS 1e-16f
#define KSPLIT 8
#define KCHUNK (C_ / KSPLIT)   // 128
#define NSTEP (KCHUNK / 16)    // 8

// ---------------- scratch ----------------
__device__ float g_part[KSPLIT * B_ * OUTF];
__device__ float g_o[B_ * OUTF];     // (k|beta|g|s0..2|gamma|e|a), e sigmoided
__device__ float g_scal[B_ * 8];     // beta,g,gamma,knorm,s0,s1,s2

// ---------------- cp.async helpers (4B only: alignment-safe everywhere) ----------------
__device__ __forceinline__ void cp_async4(void* smem_dst, const void* gmem_src, int src_bytes) {
    unsigned saddr = (unsigned)__cvta_generic_to_shared(smem_dst);
    asm volatile("cp.async.ca.shared.global [%0], [%1], 4, %2;\n"
                 :: "r"(saddr), "l"(gmem_src), "r"(src_bytes));
}
__device__ __forceinline__ void cp_async_commit() {
    asm volatile("cp.async.commit_group;\n");
}
template<int NWait>
__device__ __forceinline__ void cp_async_wait() {
    asm volatile("cp.async.wait_group %0;\n" :: "n"(NWait));
}

// ---------------- K1: split-K SGEMM, 2-stage cp.async pipeline ----------------
// 64x64 tile, 256 threads, 4x4 micro-tile, BK=16
__global__ void __launch_bounds__(256)
k1_gemm(const float* __restrict__ A,
        const float* __restrict__ Bm)
{
    __shared__ float As[2][16][65];   // [stage][kk][row] (transposed, as in R7)
    __shared__ float Bs[2][16][68];   // [stage][kk][col]

    const int tid = threadIdx.x;
    const int tx  = tid & 15;
    const int ty  = tid >> 4;
    const int row0 = blockIdx.y * 64;
    const int col0 = blockIdx.x * 64;
    const int kbeg = blockIdx.z * KCHUNK;

    // A copy: thread t -> row=t>>2, k offsets (t&3)*4 + j  (4x 4B cp.async, transposed store)
    const int ar = tid >> 2;
    const int ac = (tid & 3) * 4;
    // B copy: thread t -> kk=t>>4, cols (t&15)*4 + j       (4x 4B cp.async)
    const int bk = tid >> 4;
    const int bc = (tid & 15) * 4;
    int bbytes[4];
#pragma unroll
    for (int j = 0; j < 4; j++)
        bbytes[j] = (col0 + bc + j < OUTF) ? 4 : 0;

    float acc[4][4];
#pragma unroll
    for (int i = 0; i < 4; i++)
#pragma unroll
        for (int j = 0; j < 4; j++) acc[i][j] = 0.f;

    // prologue: stage 0
    {
        const int k0 = kbeg;
        const float* asrc = &A[(size_t)(row0 + ar) * C_ + k0 + ac];
#pragma unroll
        for (int j = 0; j < 4; j++)
            cp_async4(&As[0][ac + j][ar], asrc + j, 4);
        const float* bsrc = &Bm[(size_t)(k0 + bk) * OUTF + col0 + bc];
#pragma unroll
        for (int j = 0; j < 4; j++)
            cp_async4(&Bs[0][bk][bc + j], bsrc + j, bbytes[j]);
        cp_async_commit();
    }

#pragma unroll
    for (int t = 0; t < NSTEP; t++) {
        const int st = t & 1;
        if (t + 1 < NSTEP) {
            const int k0 = kbeg + (t + 1) * 16;
            const int sn = (t + 1) & 1;
            const float* asrc = &A[(size_t)(row0 + ar) * C_ + k0 + ac];
#pragma unroll
            for (int j = 0; j < 4; j++)
                cp_async4(&As[sn][ac + j][ar], asrc + j, 4);
            const float* bsrc = &Bm[(size_t)(k0 + bk) * OUTF + col0 + bc];
#pragma unroll
            for (int j = 0; j < 4; j++)
                cp_async4(&Bs[sn][bk][bc + j], bsrc + j, bbytes[j]);
            cp_async_commit();
            cp_async_wait<1>();
        } else {
            cp_async_wait<0>();
        }
        __syncthreads();

#pragma unroll
        for (int kk = 0; kk < 16; kk++) {
            float ra[4];
#pragma unroll
            for (int i = 0; i < 4; i++) ra[i] = As[st][kk][ty * 4 + i];
            float4 rb4 = *(const float4*)&Bs[st][kk][tx * 4];
            float rb[4] = {rb4.x, rb4.y, rb4.z, rb4.w};
#pragma unroll
            for (int i = 0; i < 4; i++)
#pragma unroll
                for (int j = 0; j < 4; j++) acc[i][j] = fmaf(ra[i], rb[j], acc[i][j]);
        }
        __syncthreads();
    }

    float* part = &g_part[(size_t)blockIdx.z * B_ * OUTF];
#pragma unroll
    for (int i = 0; i < 4; i++) {
        int row = row0 + ty * 4 + i;
#pragma unroll
        for (int j = 0; j < 4; j++) {
            int col = col0 + tx * 4 + j;
            if (col < OUTF)
                part[(size_t)row * OUTF + col] = acc[i][j];
        }
    }
}

// ---------------- K2: fused split-K reduce + bias + activations ----------------
__device__ __forceinline__ float softplus_f(float x) {
    return (x > 0.f) ? (x + log1pf(expf(-x))) : log1pf(expf(x));
}
__device__ __forceinline__ float sigmoid_f(float x) {
    return 1.f / (1.f + expf(-x));
}

__global__ void k2_redact(const float* __restrict__ bias)  // grid=B_, block=256
{
    const int b   = blockIdx.x;
    const int tid = threadIdx.x;
    __shared__ float so[OUTF];
    __shared__ float red[8];

    for (int col = tid; col < OUTF; col += 256) {
        float s = bias[col];
#pragma unroll
        for (int ks = 0; ks < KSPLIT; ks++)
            s += g_part[(size_t)ks * B_ * OUTF + (size_t)b * OUTF + col];
        so[col] = s;
    }
    __syncthreads();

    float ss = 0.f;
    if (tid < 128) { float kv = so[tid]; ss = kv * kv; }
#pragma unroll
    for (int off = 16; off > 0; off >>= 1)
        ss += __shfl_xor_sync(0xffffffffu, ss, off);
    if ((tid & 31) == 0) red[tid >> 5] = ss;
    __syncthreads();

    if (tid == 0) {
        float knorm = sqrtf(red[0] + red[1] + red[2] + red[3]);
        float beta  = softplus_f(so[M_]);
        float g     = sigmoid_f(so[M_ + 1]);
        float s0 = so[M_ + 2], s1 = so[M_ + 3], s2 = so[M_ + 4];
        float mx = fmaxf(s0, fmaxf(s1, s2));
        float e0 = expf(s0 - mx), e1 = expf(s1 - mx), e2 = expf(s2 - mx);
        float es = e0 + e1 + e2;
        float gamma = 1.f + softplus_f(so[M_ + 5]);
        float* sc = &g_scal[b * 8];
        sc[0] = beta; sc[1] = g; sc[2] = gamma; sc[3] = knorm;
        sc[4] = e0 / es; sc[5] = e1 / es; sc[6] = e2 / es;
    }

    float* o = &g_o[(size_t)b * OUTF];
    for (int col = tid; col < OUTF; col += 256) {
        float v = so[col];
        if (col >= M_ + 6 && col < 2 * M_ + 6) v = sigmoid_f(v);
        o[col] = v;
    }
}

// ---------------- KF: fused sim + weighting + update ----------------
__global__ void __launch_bounds__(1024, 1)
kF_fused(const float* __restrict__ mem,
         const float* __restrict__ w_prev,
         float* __restrict__ w_out,
         float* __restrict__ out_mem)
{
    extern __shared__ float sh[];
    float* sk   = sh;            // 128
    float* se   = sk + 128;      // 128
    float* sa   = se + 128;      // 128
    float* slog = sa + 128;      // 1024
    float* warr = slog + 1024;   // 1024
    float* sred = warr + 1024;   // 32

    const int b    = blockIdx.x;
    const int tid  = threadIdx.x;
    const int warp = tid >> 5;
    const int lane = tid & 31;

    if (tid < 128) {
        sk[tid] = g_o[(size_t)b * OUTF + tid];
        se[tid] = g_o[(size_t)b * OUTF + M_ + 6 + tid];
        sa[tid] = g_o[(size_t)b * OUTF + 2 * M_ + 6 + tid];
    }
    __syncthreads();

    const float beta  = g_scal[b * 8 + 0];
    const float g     = g_scal[b * 8 + 1];
    const float gamma = g_scal[b * 8 + 2];
    const float knorm = g_scal[b * 8 + 3];
    const float s0    = g_scal[b * 8 + 4];
    const float s1    = g_scal[b * 8 + 5];
    const float s2    = g_scal[b * 8 + 6];

    const float* memb = mem + (size_t)b * N_ * M_;

    // ---- pass 1: 8 lanes per row ----
    const int sub = lane >> 3;          // 0..3
    const int qc  = (lane & 7) * 4;     // 0..28
    float kq[4][4];
#pragma unroll
    for (int q = 0; q < 4; q++) {
        const float4 kv = *(const float4*)&sk[qc + 32 * q];
        kq[q][0] = kv.x; kq[q][1] = kv.y; kq[q][2] = kv.z; kq[q][3] = kv.w;
    }

#pragma unroll
    for (int i0 = 0; i0 < 32; i0 += 8) {
        const int n0 = warp * 32 + i0 + sub;
        const int n1 = n0 + 4;
        float4 mv0[4], mv1[4];
#pragma unroll
        for (int q = 0; q < 4; q++) {
            mv0[q] = *(const float4*)&memb[(size_t)n0 * M_ + qc + 32 * q];
            mv1[q] = *(const float4*)&memb[(size_t)n1 * M_ + qc + 32 * q];
        }
        float dot0 = 0.f, ssq0 = 0.f, dot1 = 0.f, ssq1 = 0.f;
#pragma unroll
        for (int q = 0; q < 4; q++) {
            dot0 = fmaf(mv0[q].x, kq[q][0], dot0); ssq0 = fmaf(mv0[q].x, mv0[q].x, ssq0);
            dot0 = fmaf(mv0[q].y, kq[q][1], dot0); ssq0 = fmaf(mv0[q].y, mv0[q].y, ssq0);
            dot0 = fmaf(mv0[q].z, kq[q][2], dot0); ssq0 = fmaf(mv0[q].z, mv0[q].z, ssq0);
            dot0 = fmaf(mv0[q].w, kq[q][3], dot0); ssq0 = fmaf(mv0[q].w, mv0[q].w, ssq0);
            dot1 = fmaf(mv1[q].x, kq[q][0], dot1); ssq1 = fmaf(mv1[q].x, mv1[q].x, ssq1);
            dot1 = fmaf(mv1[q].y, kq[q][1], dot1); ssq1 = fmaf(mv1[q].y, mv1[q].y, ssq1);
            dot1 = fmaf(mv1[q].z, kq[q][2], dot1); ssq1 = fmaf(mv1[q].z, mv1[q].z, ssq1);
            dot1 = fmaf(mv1[q].w, kq[q][3], dot1); ssq1 = fmaf(mv1[q].w, mv1[q].w, ssq1);
        }
#pragma unroll
        for (int off = 4; off > 0; off >>= 1) {
            dot0 += __shfl_xor_sync(0xffffffffu, dot0, off);
            ssq0 += __shfl_xor_sync(0xffffffffu, ssq0, off);
            dot1 += __shfl_xor_sync(0xffffffffu, dot1, off);
            ssq1 += __shfl_xor_sync(0xffffffffu, ssq1, off);
        }
        if ((lane & 7) == 0) {
            slog[n0] = beta * (dot0 / (sqrtf(ssq0) * knorm + EPS));
            slog[n1] = beta * (dot1 / (sqrtf(ssq1) * knorm + EPS));
        }
    }
    __syncthreads();

    // ---- softmax -> gate -> shift -> sharpen ----
    float x = slog[tid];
    float lmax = x;
#pragma unroll
    for (int off = 16; off > 0; off >>= 1)
        lmax = fmaxf(lmax, __shfl_xor_sync(0xffffffffu, lmax, off));
    if (lane == 0) sred[warp] = lmax;
    __syncthreads();
    float bmax = sred[0];
#pragma unroll
    for (int k = 1; k < 32; k++) bmax = fmaxf(bmax, sred[k]);

    float p = expf(x - bmax);
    float lsum = p;
#pragma unroll
    for (int off = 16; off > 0; off >>= 1)
        lsum += __shfl_xor_sync(0xffffffffu, lsum, off);
    __syncthreads();
    if (lane == 0) sred[warp] = lsum;
    __syncthreads();
    float bsum = 0.f;
#pragma unroll
    for (int k = 0; k < 32; k++) bsum += sred[k];
    const float inv = 1.f / bsum;

    slog[tid] = g * (p * inv) + (1.f - g) * w_prev[(size_t)b * N_ + tid];
    __syncthreads();

    float wt = s0 * slog[(tid + N_ - 1) & (N_ - 1)] + s1 * slog[tid]
             + s2 * slog[(tid + 1) & (N_ - 1)];
    float wpow = powf(wt + EPS, gamma);
    float lsum2 = wpow;
#pragma unroll
    for (int off = 16; off > 0; off >>= 1)
        lsum2 += __shfl_xor_sync(0xffffffffu, lsum2, off);
    __syncthreads();
    if (lane == 0) sred[warp] = lsum2;
    __syncthreads();
    float bsum2 = 0.f;
#pragma unroll
    for (int k = 0; k < 32; k++) bsum2 += sred[k];
    const float inv2 = 1.f / (bsum2 + EPS);

    const float wv = wpow * inv2;
    warr[tid] = wv;
    w_out[(size_t)b * N_ + tid] = wv;
    __syncthreads();

    // ---- pass 2: 8 rows in flight; reads are L2 hits ----
    const float4 ev = *(const float4*)&se[lane * 4];
    const float4 av = *(const float4*)&sa[lane * 4];
    float* outb = out_mem + (size_t)b * N_ * M_;
#pragma unroll
    for (int i0 = 0; i0 < 32; i0 += 8) {
        const int nbase = warp * 32 + i0;
        float4 mv[8];
        float wr[8];
#pragma unroll
        for (int i = 0; i < 8; i++) {
            mv[i] = __ldcs((const float4*)&memb[(size_t)(nbase + i) * M_ + lane * 4]);
            wr[i] = warr[nbase + i];
        }
#pragma unroll
        for (int i = 0; i < 8; i++) {
            float4 r;
            r.x = mv[i].x * (1.f - wr[i] * ev.x) + wr[i] * av.x;
            r.y = mv[i].y * (1.f - wr[i] * ev.y) + wr[i] * av.y;
            r.z = mv[i].z * (1.f - wr[i] * ev.z) + wr[i] * av.z;
            r.w = mv[i].w * (1.f - wr[i] * ev.w) + wr[i] * av.w;
            __stcs((float4*)&outb[(size_t)(nbase + i) * M_ + lane * 4], r);
        }
    }
}

// ---------------- launch ----------------
extern "C" void kernel_launch(void* const* d_in, const int* in_sizes, int n_in,
                              void* d_out, int out_size)
{
    const float* emb    = (const float*)d_in[0];
    const float* w_prev = (const float*)d_in[1];
    const float* mem    = (const float*)d_in[2];
    const float* fc_w   = (const float*)d_in[3];
    const float* fc_b   = (const float*)d_in[4];

    float* out_w   = (float*)d_out;
    float* out_mem = out_w + (size_t)B_ * N_;

    dim3 g1((OUTF + 63) / 64, B_ / 64, KSPLIT);
    k1_gemm<<<g1, 256>>>(emb, fc_w);
    k2_redact<<<B_, 256>>>(fc_b);

    const int smemF = 120 * 1024;   // force 1 CTA/SM (L2 residency)
    cudaFuncSetAttribute(kF_fused, cudaFuncAttributeMaxDynamicSharedMemorySize, smemF);
    kF_fused<<<B_, 1024, smemF>>>(mem, w_prev, out_w, out_mem);
}